// round 11
// baseline (speedup 1.0000x reference)
#include <cuda_runtime.h>
#include <cuda_bf16.h>
#include <math.h>
#include <cstdint>

// inputs [32,64,64,64] NCHW fp32, weight [512,64] fp32.
#define HW_    4096
#define N_TOK  131072
#define K_     512
#define D_     64
#define PITCH  36            // smem pitch in 32-bit words for bf16x2 tiles (conflict-free)

__device__ float    g_swn[K_];
__device__ uint32_t g_wbf16[K_ * 32];     // bf16x2 packed codebook, [k][d/2]
__device__ int      g_counts[K_];
__device__ float    g_partials[1024];

// ---------------- smem layout (bytes) ----------------
#define OFF_A32    0            // fp32 x [d][token] 64x128            32768
#define OFF_APK    32768        // bf16x2 A [token][PITCH]             18432
#define OFF_WPK    51200        // bf16x2 W [code][PITCH]              73728
#define OFF_SWN    124928       // 512 fp32                             2048
#define OFF_BAP    126976       // 128 fp32 best-approx                  512
#define OFF_THR    127488       // 128 fp32 thresholds                   512
#define OFF_ANRM   128000       // 128 fp32 ||x||^2                      512
#define OFF_HIST   128512       // 512 int                              2048
#define OFF_ENC    130560       // 128 int                               512
#define OFF_RED    131072       // 256 fp32                             1024
#define SMEM_TOTAL 132096

// ---------------- prep: bf16 codebook + ||w||^2 + zero counts ----------------
__global__ __launch_bounds__(512)
void vq_prep_kernel(const float* __restrict__ weight) {
    const int k = threadIdx.x;
    const float* wr = weight + (k << 6);
    float c = 0.f;
    #pragma unroll
    for (int d = 0; d < 64; d++) c = __fadd_rn(c, __fmul_rn(wr[d], wr[d]));
    g_swn[k] = c;
    #pragma unroll
    for (int d = 0; d < 64; d += 2) {
        __nv_bfloat162 p = __nv_bfloat162(__float2bfloat16_rn(wr[d]),
                                          __float2bfloat16_rn(wr[d + 1]));
        g_wbf16[(k << 5) + (d >> 1)] = *(uint32_t*)&p;
    }
    g_counts[k] = 0;
}

// mma.sync m16n8k16 row.col bf16 -> f32 (plain sm_80+ PTX; no 'a' features)
static __device__ __forceinline__ void mma16816(float& c0, float& c1, float& c2, float& c3,
                                                uint32_t a0, uint32_t a1, uint32_t a2, uint32_t a3,
                                                uint32_t b0, uint32_t b1) {
    asm volatile("mma.sync.aligned.m16n8k16.row.col.f32.bf16.bf16.f32 "
                 "{%0,%1,%2,%3}, {%4,%5,%6,%7}, {%8,%9}, {%0,%1,%2,%3};"
                 : "+f"(c0), "+f"(c1), "+f"(c2), "+f"(c3)
                 : "r"(a0), "r"(a1), "r"(a2), "r"(a3), "r"(b0), "r"(b1));
}

// exact distance: bit-validated chain fl(fl(A - 2*dot_asc) + C)
static __device__ __forceinline__ float exact_dist(const float* __restrict__ sA32,
                                                   const float4* __restrict__ wf,
                                                   int token, float A, float C) {
    float c = 0.f;
    #pragma unroll
    for (int q = 0; q < 16; q++) {
        const float4 wv = __ldg(wf + q);
        c = __fmaf_rn(sA32[((4 * q + 0) << 7) + token], wv.x, c);
        c = __fmaf_rn(sA32[((4 * q + 1) << 7) + token], wv.y, c);
        c = __fmaf_rn(sA32[((4 * q + 2) << 7) + token], wv.z, c);
        c = __fmaf_rn(sA32[((4 * q + 3) << 7) + token], wv.w, c);
    }
    const float m = __fmul_rn(2.0f, c);
    return __fadd_rn(__fadd_rn(A, -m), C);
}

// ---------------- mega kernel: HMMA screen + exact rescore + fused epilogue ----------------
__global__ __launch_bounds__(256, 1)
void vq_mega_kernel(const float* __restrict__ input, const float* __restrict__ weight,
                    float* __restrict__ out) {
    extern __shared__ char smem[];
    float*    sA32 = (float*)   (smem + OFF_A32);
    uint32_t* apk  = (uint32_t*)(smem + OFF_APK);
    uint32_t* wpk  = (uint32_t*)(smem + OFF_WPK);
    float*    sswn = (float*)   (smem + OFF_SWN);
    float*    sbap = (float*)   (smem + OFF_BAP);
    float*    sthr = (float*)   (smem + OFF_THR);
    float*    sanm = (float*)   (smem + OFF_ANRM);
    int*      shist= (int*)     (smem + OFF_HIST);
    int*      senc = (int*)     (smem + OFF_ENC);
    float*    sred = (float*)   (smem + OFF_RED);

    const int tid  = threadIdx.x;
    const int wid  = tid >> 5;
    const int lane = tid & 31;
    const int g    = lane >> 2;        // fragment row group 0..7
    const int tg   = lane & 3;         // fragment quad index 0..3
    const int R    = wid << 4;         // 16-token row base per warp
    const int token0 = blockIdx.x * 128;
    const float* ip = input + ((token0 >> 12) << 18) + (token0 & (HW_ - 1));

    // ---- load input tile: fp32 [d][token] + packed bf16x2 [token][d/2] ----
    for (int p = tid; p < 4096; p += 256) {
        const int t = p & 127, dp = p >> 7, d = dp << 1;
        const float x0 = __ldg(ip + d * HW_ + t);
        const float x1 = __ldg(ip + (d + 1) * HW_ + t);
        sA32[(d << 7) + t]       = x0;
        sA32[((d + 1) << 7) + t] = x1;
        __nv_bfloat162 pr = __nv_bfloat162(__float2bfloat16_rn(x0), __float2bfloat16_rn(x1));
        apk[t * PITCH + dp] = *(uint32_t*)&pr;
    }
    // ---- codebook + norms + hist ----
    for (int idx = tid; idx < K_ * 32; idx += 256)
        wpk[(idx >> 5) * PITCH + (idx & 31)] = g_wbf16[idx];
    sswn[tid] = g_swn[tid]; sswn[tid + 256] = g_swn[tid + 256];
    shist[tid] = 0; shist[tid + 256] = 0;
    __syncthreads();

    // ---- per-token A = ||x||^2 via validated XLA butterfly ----
    if (tid < 128) {
        float pv[32];
        #pragma unroll
        for (int t = 0; t < 32; t++) {
            const float x0 = sA32[((2 * t) << 7) + tid];
            const float x1 = sA32[((2 * t + 1) << 7) + tid];
            pv[t] = __fadd_rn(__fmul_rn(x0, x0), __fmul_rn(x1, x1));
        }
        float qv[16], rv[8], sv[4], uv[2];
        #pragma unroll
        for (int t = 0; t < 16; t++) qv[t] = __fadd_rn(pv[t], pv[t + 16]);
        #pragma unroll
        for (int t = 0; t < 8; t++)  rv[t] = __fadd_rn(qv[t], qv[t + 8]);
        #pragma unroll
        for (int t = 0; t < 4; t++)  sv[t] = __fadd_rn(rv[t], rv[t + 4]);
        #pragma unroll
        for (int t = 0; t < 2; t++)  uv[t] = __fadd_rn(sv[t], sv[t + 2]);
        sanm[tid] = __fadd_rn(uv[0], uv[1]);
    }

    // ---- preload A fragments (constant across all n-tiles): 16 regs ----
    uint32_t aw[4][4];
    #pragma unroll
    for (int ks = 0; ks < 4; ks++) {
        aw[ks][0] = apk[(R + g) * PITCH + ks * 8 + tg];
        aw[ks][1] = apk[(R + g + 8) * PITCH + ks * 8 + tg];
        aw[ks][2] = apk[(R + g) * PITCH + ks * 8 + tg + 4];
        aw[ks][3] = apk[(R + g + 8) * PITCH + ks * 8 + tg + 4];
    }

    // ---- pass 1: per-token min of approx dist ----
    float min0 = INFINITY, min1 = INFINITY;
    #pragma unroll 2
    for (int nt = 0; nt < 64; nt++) {
        float c0 = 0.f, c1 = 0.f, c2 = 0.f, c3 = 0.f;
        const int bk = (nt * 8 + g) * PITCH;
        #pragma unroll
        for (int ks = 0; ks < 4; ks++)
            mma16816(c0, c1, c2, c3, aw[ks][0], aw[ks][1], aw[ks][2], aw[ks][3],
                     wpk[bk + ks * 8 + tg], wpk[bk + ks * 8 + tg + 4]);
        const int k0 = nt * 8 + 2 * tg;
        const float ap0 = fmaf(-2.f, c0, sswn[k0]);
        const float ap1 = fmaf(-2.f, c1, sswn[k0 + 1]);
        const float ap2 = fmaf(-2.f, c2, sswn[k0]);
        const float ap3 = fmaf(-2.f, c3, sswn[k0 + 1]);
        min0 = fminf(min0, fminf(ap0, ap1));
        min1 = fminf(min1, fminf(ap2, ap3));
    }
    // reduce across the 4 quad lanes (same token rows)
    #pragma unroll
    for (int m = 1; m <= 2; m <<= 1) {
        min0 = fminf(min0, __shfl_xor_sync(0xFFFFFFFFu, min0, m));
        min1 = fminf(min1, __shfl_xor_sync(0xFFFFFFFFu, min1, m));
    }
    if (tg == 0) { sbap[R + g] = min0; sbap[R + g + 8] = min1; }
    __syncthreads();
    if (tid < 128)  // containment window: 2*bf16-rounding bound with 2x margin
        sthr[tid] = sbap[tid] + fmaxf(6e-3f, 5e-4f * sqrtf(sanm[tid]));
    __syncthreads();

    // ---- pass 2: recompute approx, exact-rescore candidates ----
    const float th0 = sthr[R + g],     th1 = sthr[R + g + 8];
    const float A0  = sanm[R + g],     A1  = sanm[R + g + 8];
    float bd0 = INFINITY, bd1 = INFINITY;
    int   bk0 = 0,        bk1 = 0;
    #pragma unroll 1
    for (int nt = 0; nt < 64; nt++) {
        float c0 = 0.f, c1 = 0.f, c2 = 0.f, c3 = 0.f;
        const int bko = (nt * 8 + g) * PITCH;
        #pragma unroll
        for (int ks = 0; ks < 4; ks++)
            mma16816(c0, c1, c2, c3, aw[ks][0], aw[ks][1], aw[ks][2], aw[ks][3],
                     wpk[bko + ks * 8 + tg], wpk[bko + ks * 8 + tg + 4]);
        const int k0 = nt * 8 + 2 * tg;
        const float ap0 = fmaf(-2.f, c0, sswn[k0]);
        const float ap1 = fmaf(-2.f, c1, sswn[k0 + 1]);
        const float ap2 = fmaf(-2.f, c2, sswn[k0]);
        const float ap3 = fmaf(-2.f, c3, sswn[k0 + 1]);
        if (ap0 <= th0) {
            const float dd = exact_dist(sA32, (const float4*)(weight + (k0 << 6)), R + g, A0, sswn[k0]);
            if (dd < bd0) { bd0 = dd; bk0 = k0; }
        }
        if (ap1 <= th0) {
            const float dd = exact_dist(sA32, (const float4*)(weight + ((k0 + 1) << 6)), R + g, A0, sswn[k0 + 1]);
            if (dd < bd0) { bd0 = dd; bk0 = k0 + 1; }
        }
        if (ap2 <= th1) {
            const float dd = exact_dist(sA32, (const float4*)(weight + (k0 << 6)), R + g + 8, A1, sswn[k0]);
            if (dd < bd1) { bd1 = dd; bk1 = k0; }
        }
        if (ap3 <= th1) {
            const float dd = exact_dist(sA32, (const float4*)(weight + ((k0 + 1) << 6)), R + g + 8, A1, sswn[k0 + 1]);
            if (dd < bd1) { bd1 = dd; bk1 = k0 + 1; }
        }
    }
    // lexicographic (dist, k) merge across quad -> first-index argmin semantics
    #pragma unroll
    for (int m = 1; m <= 2; m <<= 1) {
        const float od0 = __shfl_xor_sync(0xFFFFFFFFu, bd0, m);
        const int   ok0 = __shfl_xor_sync(0xFFFFFFFFu, bk0, m);
        if (od0 < bd0 || (od0 == bd0 && ok0 < bk0)) { bd0 = od0; bk0 = ok0; }
        const float od1 = __shfl_xor_sync(0xFFFFFFFFu, bd1, m);
        const int   ok1 = __shfl_xor_sync(0xFFFFFFFFu, bk1, m);
        if (od1 < bd1 || (od1 == bd1 && ok1 < bk1)) { bd1 = od1; bk1 = ok1; }
    }
    if (tg == 0) {
        senc[R + g] = bk0;      atomicAdd(&shist[bk0], 1);
        senc[R + g + 8] = bk1;  atomicAdd(&shist[bk1], 1);
    }
    __syncthreads();

    // ---- fused epilogue: straight-through output + MSE partial ----
    {
        const int t  = tid >> 1;
        const int db = (tid & 1) << 5;
        const int k  = senc[t];
        const float4* wf = (const float4*)(weight + (k << 6) + db);
        float4* o4 = (float4*)(out + (size_t)(token0 + t) * 64 + db);
        float local = 0.f;
        #pragma unroll
        for (int q = 0; q < 8; q++) {
            const float4 wv = __ldg(wf + q);
            const int d = db + 4 * q;
            const float x0 = sA32[((d + 0) << 7) + t];
            const float x1 = sA32[((d + 1) << 7) + t];
            const float x2 = sA32[((d + 2) << 7) + t];
            const float x3 = sA32[((d + 3) << 7) + t];
            const float t0 = __fadd_rn(wv.x, -x0);
            const float t1 = __fadd_rn(wv.y, -x1);
            const float t2 = __fadd_rn(wv.z, -x2);
            const float t3 = __fadd_rn(wv.w, -x3);
            float4 ov;
            ov.x = __fadd_rn(x0, t0); ov.y = __fadd_rn(x1, t1);
            ov.z = __fadd_rn(x2, t2); ov.w = __fadd_rn(x3, t3);
            o4[q] = ov;
            local += t0 * t0 + t1 * t1 + t2 * t2 + t3 * t3;
        }
        sred[tid] = local;
    }
    __syncthreads();
    #pragma unroll
    for (int s = 128; s > 0; s >>= 1) {
        if (tid < s) sred[tid] += sred[tid + s];
        __syncthreads();
    }
    if (tid == 0) g_partials[blockIdx.x] = sred[0];

    if (shist[tid])       atomicAdd(&g_counts[tid],       shist[tid]);
    if (shist[tid + 256]) atomicAdd(&g_counts[tid + 256], shist[tid + 256]);
}

// ---------------- final: loss + perplexity ----------------
__global__ __launch_bounds__(512)
void vq_final_kernel(float* __restrict__ out, int nq, float inv_nq) {
    __shared__ float red[512];
    const int t = threadIdx.x;
    red[t] = g_partials[t] + g_partials[t + 512];
    __syncthreads();
    #pragma unroll
    for (int s = 256; s > 0; s >>= 1) {
        if (t < s) red[t] += red[t + s];
        __syncthreads();
    }
    const float loss = 1.25f * red[0] * inv_nq;
    __syncthreads();
    const float pf = (float)g_counts[t] * (1.0f / (float)N_TOK);
    red[t] = pf * __logf(__fadd_rn(pf, 1e-10f));
    __syncthreads();
    #pragma unroll
    for (int s = 256; s > 0; s >>= 1) {
        if (t < s) red[t] += red[t + s];
        __syncthreads();
    }
    if (t == 0) {
        out[nq]     = loss;
        out[nq + 1] = __expf(-red[0]);
    }
}

extern "C" void kernel_launch(void* const* d_in, const int* in_sizes, int n_in,
                              void* d_out, int out_size) {
    const float* input  = (const float*)d_in[0];
    const float* weight = (const float*)d_in[1];
    float*       out    = (float*)d_out;
    const int nq = out_size - 2;

    cudaFuncSetAttribute(vq_mega_kernel,
                         cudaFuncAttributeMaxDynamicSharedMemorySize, SMEM_TOTAL);

    vq_prep_kernel<<<1, 512>>>(weight);
    vq_mega_kernel<<<N_TOK / 128, 256, SMEM_TOTAL>>>(input, weight, out);
    vq_final_kernel<<<1, 512>>>(out, nq, 1.0f / (float)nq);
}